// round 3
// baseline (speedup 1.0000x reference)
#include <cuda_runtime.h>
#include <cuda_fp16.h>
#include <math.h>

#define NN 20000
#define EE 320000
#define E2 (2*EE)
#define HH 64

// ---------------- static scratch (no allocations allowed) ----------------
__device__ int   g_cnt[NN];
__device__ int   g_ptr[NN + 1];
__device__ int   g_rank[E2];
__device__ int   g_src[E2];
__device__ float g_ea5[E2 * 5];
__device__ float g_deg[NN];
__device__ float g_dis[NN];
__device__ float g_buf[5][NN * HH];
__device__ __align__(16) __half g_hbuf[2][NN * HH];   // fp16 shadows for gathered tensors

// ---------------- setup kernels ----------------

__global__ void k_zero_counts()
{
    int i = blockIdx.x * blockDim.x + threadIdx.x;
    if (i < NN) g_cnt[i] = 0;
}

// count in-degree for both directions; remember each edge's rank within its
// destination segment (atomicAdd return) so scatter needs no atomics.
__global__ void k_count(const int* __restrict__ ei)
{
    int j = blockIdx.x * blockDim.x + threadIdx.x;
    if (j >= EE) return;
    int a = ei[j], b = ei[EE + j];
    int r0 = atomicAdd(&g_cnt[b], 1);   // forward edge: dst = b
    int r1 = atomicAdd(&g_cnt[a], 1);   // reverse edge: dst = a
    g_rank[j]      = r0;
    g_rank[EE + j] = r1;
}

// single-block exclusive scan over g_cnt -> g_ptr, plus deg / rsqrt(deg)
__global__ void k_scan()
{
    __shared__ int sw[32];
    __shared__ int sTotal;
    __shared__ int sCarry;
    int t = threadIdx.x;
    int lane = t & 31, w = t >> 5;
    if (t == 0) sCarry = 0;
    for (int base = 0; base < NN; base += 1024) {
        __syncthreads();
        int carry = sCarry;
        int i = base + t;
        int v = (i < NN) ? g_cnt[i] : 0;
        int x = v;
        #pragma unroll
        for (int d = 1; d < 32; d <<= 1) {
            int y = __shfl_up_sync(0xffffffffu, x, d);
            if (lane >= d) x += y;
        }
        if (lane == 31) sw[w] = x;
        __syncthreads();
        if (w == 0) {
            int y = sw[lane];
            #pragma unroll
            for (int d = 1; d < 32; d <<= 1) {
                int z = __shfl_up_sync(0xffffffffu, y, d);
                if (lane >= d) y += z;
            }
            sw[lane] = y;
            if (lane == 31) sTotal = y;
        }
        __syncthreads();
        int incl = x + ((w > 0) ? sw[w - 1] : 0);
        if (i < NN) {
            g_ptr[i] = carry + incl - v;
            float df = (float)v;
            g_deg[i] = df;
            g_dis[i] = (v > 0) ? rsqrtf(df) : 0.f;
        }
        __syncthreads();
        if (t == 0) sCarry = carry + sTotal;
    }
    __syncthreads();
    if (t == 0) g_ptr[NN] = sCarry;
}

// atomic-free scatter using precomputed ranks; handles both directions.
__global__ void k_scatter(const int* __restrict__ ei, const float* __restrict__ eattr)
{
    int j = blockIdx.x * blockDim.x + threadIdx.x;
    if (j >= EE) return;
    int a = ei[j], b = ei[EE + j];
    float e0 = eattr[j * 5 + 0];
    float e1 = eattr[j * 5 + 1];
    float e2 = eattr[j * 5 + 2];
    float e3 = eattr[j * 5 + 3];
    float e4 = eattr[j * 5 + 4];
    int p0 = g_ptr[b] + g_rank[j];        // forward: src=a, dst=b
    int p1 = g_ptr[a] + g_rank[EE + j];   // reverse: src=b, dst=a
    g_src[p0] = a;
    g_src[p1] = b;
    float* q0 = g_ea5 + (size_t)p0 * 5;
    q0[0] = e0; q0[1] = e1; q0[2] = e2; q0[3] = e3; q0[4] = e4;
    float* q1 = g_ea5 + (size_t)p1 * 5;
    q1[0] = e0; q1[1] = e1; q1[2] = e2; q1[3] = e3; q1[4] = e4;
}

// ---------------- layer kernels ----------------

// first layer pre: XDb = x@W1[0:6]+b1 (fp32), XSh = x@W1[6:12] (fp16 shadow)
__global__ void k_pre0(const float* __restrict__ data_x,
                       const float* __restrict__ W1, const float* __restrict__ b1,
                       float* __restrict__ XDb, __half* __restrict__ XSh)
{
    __shared__ float sW[12 * 64];
    int tid = threadIdx.x;
    for (int i = tid; i < 12 * 64; i += 256) sW[i] = W1[i];
    __syncthreads();
    int gid = blockIdx.x * 256 + tid;
    int v = gid >> 7;
    int j = gid & 127;
    if (v >= NN) return;
    const float* xr = data_x + v * 16 + 4;
    float x0 = xr[0], x1 = xr[1], x2 = xr[2], x3 = xr[3], x4 = xr[4], x5 = xr[5];
    if (j < 64) {
        float acc = b1[j];
        acc += x0 * sW[0 * 64 + j]; acc += x1 * sW[1 * 64 + j];
        acc += x2 * sW[2 * 64 + j]; acc += x3 * sW[3 * 64 + j];
        acc += x4 * sW[4 * 64 + j]; acc += x5 * sW[5 * 64 + j];
        XDb[v * 64 + j] = acc;
    } else {
        int c = j - 64;
        float acc = 0.f;
        acc += x0 * sW[6 * 64 + c];  acc += x1 * sW[7 * 64 + c];
        acc += x2 * sW[8 * 64 + c];  acc += x3 * sW[9 * 64 + c];
        acc += x4 * sW[10 * 64 + c]; acc += x5 * sW[11 * 64 + c];
        XSh[v * 64 + c] = __float2half_rn(acc);
    }
}

// generic fp32 GEMM: out = act( sum_seg A_seg@W_seg + bias*(degscale?deg:1) )
// optional fp16 shadow output (for downstream gathers).
__global__ void __launch_bounds__(256)
k_gemm64(const float* A0, const float* A1, const float* A2, const float* A3,
         int nA, const float* __restrict__ W, const float* __restrict__ bias,
         const float* __restrict__ degscale, float* __restrict__ out,
         __half* __restrict__ out_h, int do_relu, int n)
{
    __shared__ float sW[64 * 64];
    __shared__ float sA[64 * 68];
    const int tid = threadIdx.x;
    const int rowBase = blockIdx.x * 64;
    const int c0 = (tid & 15) * 4;
    const int r0 = (tid >> 4) * 4;
    float acc[4][4] = {};
    const float* As[4] = {A0, A1, A2, A3};

    for (int seg = 0; seg < nA; ++seg) {
        const float* A = As[seg];
        const float4* Wv = (const float4*)(W + seg * 64 * 64);
        #pragma unroll
        for (int i = 0; i < 4; ++i)
            ((float4*)sW)[tid + i * 256] = Wv[tid + i * 256];
        int lr = tid >> 4;
        int lc = (tid & 15) * 4;
        #pragma unroll
        for (int i = 0; i < 4; ++i) {
            int r = lr + i * 16;
            int gr = rowBase + r;
            float4 v = make_float4(0.f, 0.f, 0.f, 0.f);
            if (gr < n) v = *(const float4*)(A + (size_t)gr * 64 + lc);
            *(float4*)(&sA[r * 68 + lc]) = v;
        }
        __syncthreads();
        #pragma unroll
        for (int k = 0; k < 64; ++k) {
            float4 b = *(const float4*)(&sW[k * 64 + c0]);
            float a0 = sA[(r0 + 0) * 68 + k];
            float a1 = sA[(r0 + 1) * 68 + k];
            float a2 = sA[(r0 + 2) * 68 + k];
            float a3 = sA[(r0 + 3) * 68 + k];
            acc[0][0] += a0 * b.x; acc[0][1] += a0 * b.y; acc[0][2] += a0 * b.z; acc[0][3] += a0 * b.w;
            acc[1][0] += a1 * b.x; acc[1][1] += a1 * b.y; acc[1][2] += a1 * b.z; acc[1][3] += a1 * b.w;
            acc[2][0] += a2 * b.x; acc[2][1] += a2 * b.y; acc[2][2] += a2 * b.z; acc[2][3] += a2 * b.w;
            acc[3][0] += a3 * b.x; acc[3][1] += a3 * b.y; acc[3][2] += a3 * b.z; acc[3][3] += a3 * b.w;
        }
        __syncthreads();
    }

    float4 bv = make_float4(0.f, 0.f, 0.f, 0.f);
    if (bias) bv = *(const float4*)(bias + c0);
    #pragma unroll
    for (int i = 0; i < 4; ++i) {
        int gr = rowBase + r0 + i;
        if (gr < n) {
            float s = degscale ? degscale[gr] : 1.0f;
            float4 o;
            o.x = acc[i][0] + bv.x * s;
            o.y = acc[i][1] + bv.y * s;
            o.z = acc[i][2] + bv.z * s;
            o.w = acc[i][3] + bv.w * s;
            if (do_relu) {
                o.x = fmaxf(o.x, 0.f); o.y = fmaxf(o.y, 0.f);
                o.z = fmaxf(o.z, 0.f); o.w = fmaxf(o.w, 0.f);
            }
            *(float4*)(out + (size_t)gr * 64 + c0) = o;
            if (out_h) {
                __half2* oh = (__half2*)(out_h + (size_t)gr * 64 + c0);
                oh[0] = __floats2half2_rn(o.x, o.y);
                oh[1] = __floats2half2_rn(o.z, o.w);
            }
        }
    }
}

// dual GEMM: out0 = A@Wa + ba (fp32), out1h = A@Wb (fp16 shadow); A loaded once
__global__ void __launch_bounds__(256)
k_gemm64_dual(const float* __restrict__ A, const float* __restrict__ Wa,
              const float* __restrict__ ba, const float* __restrict__ Wb,
              float* __restrict__ out0, __half* __restrict__ out1h, int n)
{
    __shared__ float sW[64 * 64];
    __shared__ float sA[64 * 68];
    const int tid = threadIdx.x;
    const int rowBase = blockIdx.x * 64;
    const int c0 = (tid & 15) * 4;
    const int r0 = (tid >> 4) * 4;
    const int lr = tid >> 4;
    const int lc = (tid & 15) * 4;

    #pragma unroll
    for (int i = 0; i < 4; ++i) {
        int r = lr + i * 16;
        int gr = rowBase + r;
        float4 v = make_float4(0.f, 0.f, 0.f, 0.f);
        if (gr < n) v = *(const float4*)(A + (size_t)gr * 64 + lc);
        *(float4*)(&sA[r * 68 + lc]) = v;
    }

    #pragma unroll
    for (int half = 0; half < 2; ++half) {
        const float4* Wv = (const float4*)(half ? Wb : Wa);
        #pragma unroll
        for (int i = 0; i < 4; ++i)
            ((float4*)sW)[tid + i * 256] = Wv[tid + i * 256];
        __syncthreads();
        float acc[4][4] = {};
        #pragma unroll
        for (int k = 0; k < 64; ++k) {
            float4 b = *(const float4*)(&sW[k * 64 + c0]);
            float a0 = sA[(r0 + 0) * 68 + k];
            float a1 = sA[(r0 + 1) * 68 + k];
            float a2 = sA[(r0 + 2) * 68 + k];
            float a3 = sA[(r0 + 3) * 68 + k];
            acc[0][0] += a0 * b.x; acc[0][1] += a0 * b.y; acc[0][2] += a0 * b.z; acc[0][3] += a0 * b.w;
            acc[1][0] += a1 * b.x; acc[1][1] += a1 * b.y; acc[1][2] += a1 * b.z; acc[1][3] += a1 * b.w;
            acc[2][0] += a2 * b.x; acc[2][1] += a2 * b.y; acc[2][2] += a2 * b.z; acc[2][3] += a2 * b.w;
            acc[3][0] += a3 * b.x; acc[3][1] += a3 * b.y; acc[3][2] += a3 * b.z; acc[3][3] += a3 * b.w;
        }
        if (half == 0) {
            float4 bv = make_float4(0.f, 0.f, 0.f, 0.f);
            if (ba) bv = *(const float4*)(ba + c0);
            #pragma unroll
            for (int i = 0; i < 4; ++i) {
                int gr = rowBase + r0 + i;
                if (gr < n) {
                    float4 o;
                    o.x = acc[i][0] + bv.x; o.y = acc[i][1] + bv.y;
                    o.z = acc[i][2] + bv.z; o.w = acc[i][3] + bv.w;
                    *(float4*)(out0 + (size_t)gr * 64 + c0) = o;
                }
            }
        } else {
            #pragma unroll
            for (int i = 0; i < 4; ++i) {
                int gr = rowBase + r0 + i;
                if (gr < n) {
                    __half2* oh = (__half2*)(out1h + (size_t)gr * 64 + c0);
                    oh[0] = __floats2half2_rn(acc[i][0], acc[i][1]);
                    oh[1] = __floats2half2_rn(acc[i][2], acc[i][3]);
                }
            }
        }
        __syncthreads();
    }
}

// edge aggregation: agg[v] = sum_{e in in(v)} relu( XDb[v] + XS[src_e] + ea_e@W1e )
// XS gathered from fp16 shadow (1 cache line per edge per warp).
__global__ void __launch_bounds__(256)
k_edge(const float* __restrict__ XDb, const __half* __restrict__ XSh,
       const float* __restrict__ W1e, float* __restrict__ agg)
{
    __shared__ float sE[5 * 64];
    int tid = threadIdx.x;
    for (int i = tid; i < 5 * 64; i += 256) sE[i] = W1e[i];
    __syncthreads();
    int wid = (blockIdx.x * 256 + tid) >> 5;
    int lane = tid & 31;
    if (wid >= NN) return;
    int c0 = lane * 2;
    float xd0 = XDb[wid * 64 + c0], xd1 = XDb[wid * 64 + c0 + 1];
    float w0[5], w1[5];
    #pragma unroll
    for (int k = 0; k < 5; ++k) { w0[k] = sE[k * 64 + c0]; w1[k] = sE[k * 64 + c0 + 1]; }
    const __half2* XS2 = (const __half2*)XSh;
    int e0 = g_ptr[wid], e1 = g_ptr[wid + 1];
    float acc0 = 0.f, acc1 = 0.f;
    int e = e0;
    int eend4 = e0 + ((e1 - e0) & ~3);
    for (; e < eend4; e += 4) {
        int s0 = g_src[e + 0], s1 = g_src[e + 1], s2 = g_src[e + 2], s3 = g_src[e + 3];
        float q0 = (lane < 5) ? g_ea5[(e + 0) * 5 + lane] : 0.f;
        float q1 = (lane < 5) ? g_ea5[(e + 1) * 5 + lane] : 0.f;
        float q2 = (lane < 5) ? g_ea5[(e + 2) * 5 + lane] : 0.f;
        float q3 = (lane < 5) ? g_ea5[(e + 3) * 5 + lane] : 0.f;
        float2 v0 = __half22float2(XS2[(size_t)s0 * 32 + lane]);
        float2 v1 = __half22float2(XS2[(size_t)s1 * 32 + lane]);
        float2 v2 = __half22float2(XS2[(size_t)s2 * 32 + lane]);
        float2 v3 = __half22float2(XS2[(size_t)s3 * 32 + lane]);
        float p0, p1;
        p0 = xd0 + v0.x; p1 = xd1 + v0.y;
        #pragma unroll
        for (int k = 0; k < 5; ++k) { float ek = __shfl_sync(0xffffffffu, q0, k); p0 += ek * w0[k]; p1 += ek * w1[k]; }
        acc0 += fmaxf(p0, 0.f); acc1 += fmaxf(p1, 0.f);
        p0 = xd0 + v1.x; p1 = xd1 + v1.y;
        #pragma unroll
        for (int k = 0; k < 5; ++k) { float ek = __shfl_sync(0xffffffffu, q1, k); p0 += ek * w0[k]; p1 += ek * w1[k]; }
        acc0 += fmaxf(p0, 0.f); acc1 += fmaxf(p1, 0.f);
        p0 = xd0 + v2.x; p1 = xd1 + v2.y;
        #pragma unroll
        for (int k = 0; k < 5; ++k) { float ek = __shfl_sync(0xffffffffu, q2, k); p0 += ek * w0[k]; p1 += ek * w1[k]; }
        acc0 += fmaxf(p0, 0.f); acc1 += fmaxf(p1, 0.f);
        p0 = xd0 + v3.x; p1 = xd1 + v3.y;
        #pragma unroll
        for (int k = 0; k < 5; ++k) { float ek = __shfl_sync(0xffffffffu, q3, k); p0 += ek * w0[k]; p1 += ek * w1[k]; }
        acc0 += fmaxf(p0, 0.f); acc1 += fmaxf(p1, 0.f);
    }
    for (; e < e1; ++e) {
        int s = g_src[e];
        float q = (lane < 5) ? g_ea5[e * 5 + lane] : 0.f;
        float2 v = __half22float2(XS2[(size_t)s * 32 + lane]);
        float p0 = xd0 + v.x, p1 = xd1 + v.y;
        #pragma unroll
        for (int k = 0; k < 5; ++k) { float ek = __shfl_sync(0xffffffffu, q, k); p0 += ek * w0[k]; p1 += ek * w1[k]; }
        acc0 += fmaxf(p0, 0.f); acc1 += fmaxf(p1, 0.f);
    }
    float2 o; o.x = acc0; o.y = acc1;
    *(float2*)(agg + (size_t)wid * 64 + c0) = o;
}

// TAGConv propagation: Hn[v] = dis[v] * sum_e dis[src_e] * H[src_e]
// reads fp16 shadow; writes fp32 (for GEMM) and optional fp16 shadow (next hop)
__global__ void __launch_bounds__(256)
k_prop(const __half* __restrict__ Hh, float* __restrict__ Hn,
       __half* __restrict__ Hnh)
{
    int tid = threadIdx.x;
    int wid = (blockIdx.x * 256 + tid) >> 5;
    int lane = tid & 31;
    if (wid >= NN) return;
    float dd = g_dis[wid];
    const __half2* H2 = (const __half2*)Hh;
    int e0 = g_ptr[wid], e1 = g_ptr[wid + 1];
    float acc0 = 0.f, acc1 = 0.f;
    int e = e0;
    int eend8 = e0 + ((e1 - e0) & ~7);
    for (; e < eend8; e += 8) {
        int s[8];
        #pragma unroll
        for (int i = 0; i < 8; ++i) s[i] = g_src[e + i];
        float nm[8];
        #pragma unroll
        for (int i = 0; i < 8; ++i) nm[i] = g_dis[s[i]];
        float2 v[8];
        #pragma unroll
        for (int i = 0; i < 8; ++i) v[i] = __half22float2(H2[(size_t)s[i] * 32 + lane]);
        #pragma unroll
        for (int i = 0; i < 8; ++i) { acc0 += nm[i] * v[i].x; acc1 += nm[i] * v[i].y; }
    }
    for (; e < e1; ++e) {
        int s = g_src[e];
        float nr = g_dis[s];
        float2 v = __half22float2(H2[(size_t)s * 32 + lane]);
        acc0 += nr * v.x; acc1 += nr * v.y;
    }
    acc0 *= dd; acc1 *= dd;
    int c0 = lane * 2;
    float2 o; o.x = acc0; o.y = acc1;
    *(float2*)(Hn + (size_t)wid * 64 + c0) = o;
    if (Hnh)
        ((__half2*)Hnh)[(size_t)wid * 32 + lane] = __floats2half2_rn(acc0, acc1);
}

// final layer post: out[v][c] = agg[v][:]@W2[:,c] + deg[v]*b2[c]   (64x6, no relu)
__global__ void __launch_bounds__(192)
k_post_last(const float* __restrict__ agg, const float* __restrict__ W2,
            const float* __restrict__ b2, float* __restrict__ out)
{
    __shared__ float sW[64 * 6];
    __shared__ float sb[6];
    int tid = threadIdx.x;
    for (int i = tid; i < 64 * 6; i += 192) sW[i] = W2[i];
    if (tid < 6) sb[tid] = b2[tid];
    __syncthreads();
    int gid = blockIdx.x * 192 + tid;
    int v = gid / 6;
    int c = gid - v * 6;
    if (v >= NN) return;
    const float* ar = agg + (size_t)v * 64;
    float acc = 0.f;
    #pragma unroll
    for (int k = 0; k < 64; ++k) acc += ar[k] * sW[k * 6 + c];
    out[v * 6 + c] = acc + g_deg[v] * sb[c];
}

// ---------------- host ----------------

extern "C" void kernel_launch(void* const* d_in, const int* in_sizes, int n_in,
                              void* d_out, int out_size)
{
    const float* data_x     = (const float*)d_in[0];
    const int*   edge_index = (const int*)  d_in[1];
    const float* edge_attr  = (const float*)d_in[2];
    const float* ea0_W1     = (const float*)d_in[3];
    const float* ea0_b1     = (const float*)d_in[4];
    const float* ea0_W2     = (const float*)d_in[5];
    const float* ea0_b2     = (const float*)d_in[6];
    const float* eam_W1     = (const float*)d_in[7];
    const float* eam_b1     = (const float*)d_in[8];
    const float* eam_W2     = (const float*)d_in[9];
    const float* eam_b2     = (const float*)d_in[10];
    const float* eal_W1     = (const float*)d_in[11];
    const float* eal_b1     = (const float*)d_in[12];
    const float* eal_W2     = (const float*)d_in[13];
    const float* eal_b2     = (const float*)d_in[14];
    const float* tag_W      = (const float*)d_in[15];
    const float* tag_b      = (const float*)d_in[16];
    float* out = (float*)d_out;

    float* pBuf = nullptr;
    float* pDeg = nullptr;
    __half* pH = nullptr;
    cudaGetSymbolAddress((void**)&pBuf, g_buf);
    cudaGetSymbolAddress((void**)&pDeg, g_deg);
    cudaGetSymbolAddress((void**)&pH, g_hbuf);
    float* B0 = pBuf + 0 * (size_t)NN * HH;
    float* B1 = pBuf + 1 * (size_t)NN * HH;
    float* B2 = pBuf + 2 * (size_t)NN * HH;
    float* B3 = pBuf + 3 * (size_t)NN * HH;
    float* B4 = pBuf + 4 * (size_t)NN * HH;
    __half* HB0 = pH + 0 * (size_t)NN * HH;
    __half* HB1 = pH + 1 * (size_t)NN * HH;

    const int EB = (EE + 255) / 256;        // edge-parallel blocks
    const int WB = (NN * 32 + 255) / 256;   // warp-per-node blocks
    const int GB = (NN + 63) / 64;          // gemm blocks

    // CSR build
    k_zero_counts<<<(NN + 255) / 256, 256>>>();
    k_count<<<EB, 256>>>(edge_index);
    k_scan<<<1, 1024>>>();
    k_scatter<<<EB, 256>>>(edge_index, edge_attr);

    // layer 1: edge_agg ea0  (x = data_x[:,4:10])
    k_pre0<<<(NN * 128 + 255) / 256, 256>>>(data_x, ea0_W1, ea0_b1, B0, HB0);
    k_edge<<<WB, 256>>>(B0, HB0, ea0_W1 + 12 * 64, B2);
    k_gemm64<<<GB, 256>>>(B2, nullptr, nullptr, nullptr, 1, ea0_W2, ea0_b2, pDeg,
                          B3, HB0, 1, NN);
    float* x = B3;   // fp16 shadow of x in HB0

    for (int l = 0; l < 3; ++l) {
        // tagconv l: 3 propagation hops, shadows ping-pong HB0/HB1
        k_prop<<<WB, 256>>>(HB0, B0, HB1);
        k_prop<<<WB, 256>>>(HB1, B1, HB0);
        k_prop<<<WB, 256>>>(HB0, B2, nullptr);
        k_gemm64<<<GB, 256>>>(x, B0, B1, B2, 4, tag_W + (size_t)l * 4 * 64 * 64,
                              tag_b + l * 64, nullptr, B4, HB0, 1, NN);
        x = B4;   // shadow in HB0

        if (l < 2) {
            // mid edge_agg l
            const float* W1 = eam_W1 + (size_t)l * 133 * 64;
            const float* b1 = eam_b1 + l * 64;
            const float* W2 = eam_W2 + (size_t)l * 64 * 64;
            const float* b2 = eam_b2 + l * 64;
            k_gemm64_dual<<<GB, 256>>>(x, W1, b1, W1 + 64 * 64, B0, HB1, NN);
            k_edge<<<WB, 256>>>(B0, HB1, W1 + 128 * 64, B2);
            k_gemm64<<<GB, 256>>>(B2, nullptr, nullptr, nullptr, 1, W2, b2, pDeg,
                                  B3, HB0, 1, NN);
            x = B3;   // shadow in HB0
        }
    }

    // final edge_agg (64 -> 6)
    k_gemm64_dual<<<GB, 256>>>(x, eal_W1, eal_b1, eal_W1 + 64 * 64, B0, HB1, NN);
    k_edge<<<WB, 256>>>(B0, HB1, eal_W1 + 128 * 64, B2);
    k_post_last<<<(NN * 6 + 191) / 192, 192>>>(B2, eal_W2, eal_b2, out);
}

// round 8
// speedup vs baseline: 1.0760x; 1.0760x over previous
#include <cuda_runtime.h>
#include <cuda_fp16.h>
#include <stdint.h>
#include <math.h>

#define NN 20000
#define EE 320000
#define E2 (2*EE)
#define HH 64

// ---------------- static scratch (no allocations allowed) ----------------
__device__ int   g_cnt[NN];
__device__ int   g_ptr[NN + 1];
__device__ int   g_rank[E2];
__device__ int   g_src[E2];
__device__ float g_ea5[E2 * 5];
__device__ float g_deg[NN];
__device__ float g_dis[NN];
__device__ float g_buf[5][NN * HH];

// ---------------- setup kernels ----------------

__global__ void k_zero_counts()
{
    int i = blockIdx.x * blockDim.x + threadIdx.x;
    if (i < NN) g_cnt[i] = 0;
}

// count in-degree for both directions; remember each edge's rank within its
// destination segment (atomicAdd return) so scatter needs no atomics.
__global__ void k_count(const int* __restrict__ ei)
{
    int j = blockIdx.x * blockDim.x + threadIdx.x;
    if (j >= EE) return;
    int a = ei[j], b = ei[EE + j];
    int r0 = atomicAdd(&g_cnt[b], 1);
    int r1 = atomicAdd(&g_cnt[a], 1);
    g_rank[j]      = r0;
    g_rank[EE + j] = r1;
}

// single-block exclusive scan over g_cnt -> g_ptr, plus deg / rsqrt(deg)
__global__ void k_scan()
{
    __shared__ int sw[32];
    __shared__ int sTotal;
    __shared__ int sCarry;
    int t = threadIdx.x;
    int lane = t & 31, w = t >> 5;
    if (t == 0) sCarry = 0;
    for (int base = 0; base < NN; base += 1024) {
        __syncthreads();
        int carry = sCarry;
        int i = base + t;
        int v = (i < NN) ? g_cnt[i] : 0;
        int x = v;
        #pragma unroll
        for (int d = 1; d < 32; d <<= 1) {
            int y = __shfl_up_sync(0xffffffffu, x, d);
            if (lane >= d) x += y;
        }
        if (lane == 31) sw[w] = x;
        __syncthreads();
        if (w == 0) {
            int y = sw[lane];
            #pragma unroll
            for (int d = 1; d < 32; d <<= 1) {
                int z = __shfl_up_sync(0xffffffffu, y, d);
                if (lane >= d) y += z;
            }
            sw[lane] = y;
            if (lane == 31) sTotal = y;
        }
        __syncthreads();
        int incl = x + ((w > 0) ? sw[w - 1] : 0);
        if (i < NN) {
            g_ptr[i] = carry + incl - v;
            float df = (float)v;
            g_deg[i] = df;
            g_dis[i] = (v > 0) ? rsqrtf(df) : 0.f;
        }
        __syncthreads();
        if (t == 0) sCarry = carry + sTotal;
    }
    __syncthreads();
    if (t == 0) g_ptr[NN] = sCarry;
}

// atomic-free scatter using precomputed ranks; handles both directions.
__global__ void k_scatter(const int* __restrict__ ei, const float* __restrict__ eattr)
{
    int j = blockIdx.x * blockDim.x + threadIdx.x;
    if (j >= EE) return;
    int a = ei[j], b = ei[EE + j];
    float e0 = eattr[j * 5 + 0];
    float e1 = eattr[j * 5 + 1];
    float e2 = eattr[j * 5 + 2];
    float e3 = eattr[j * 5 + 3];
    float e4 = eattr[j * 5 + 4];
    int p0 = g_ptr[b] + g_rank[j];
    int p1 = g_ptr[a] + g_rank[EE + j];
    g_src[p0] = a;
    g_src[p1] = b;
    float* q0 = g_ea5 + (size_t)p0 * 5;
    q0[0] = e0; q0[1] = e1; q0[2] = e2; q0[3] = e3; q0[4] = e4;
    float* q1 = g_ea5 + (size_t)p1 * 5;
    q1[0] = e0; q1[1] = e1; q1[2] = e2; q1[3] = e3; q1[4] = e4;
}

// ---------------- layer kernels ----------------

// first layer pre: XDb = x@W1[0:6]+b1, XS = x@W1[6:12]  (x = data_x[:,4:10])
__global__ void k_pre0(const float* __restrict__ data_x,
                       const float* __restrict__ W1, const float* __restrict__ b1,
                       float* __restrict__ XDb, float* __restrict__ XS)
{
    __shared__ float sW[12 * 64];
    int tid = threadIdx.x;
    for (int i = tid; i < 12 * 64; i += 256) sW[i] = W1[i];
    __syncthreads();
    int gid = blockIdx.x * 256 + tid;
    int v = gid >> 7;
    int j = gid & 127;
    if (v >= NN) return;
    const float* xr = data_x + v * 16 + 4;
    float x0 = xr[0], x1 = xr[1], x2 = xr[2], x3 = xr[3], x4 = xr[4], x5 = xr[5];
    if (j < 64) {
        float acc = b1[j];
        acc += x0 * sW[0 * 64 + j]; acc += x1 * sW[1 * 64 + j];
        acc += x2 * sW[2 * 64 + j]; acc += x3 * sW[3 * 64 + j];
        acc += x4 * sW[4 * 64 + j]; acc += x5 * sW[5 * 64 + j];
        XDb[v * 64 + j] = acc;
    } else {
        int c = j - 64;
        float acc = 0.f;
        acc += x0 * sW[6 * 64 + c];  acc += x1 * sW[7 * 64 + c];
        acc += x2 * sW[8 * 64 + c];  acc += x3 * sW[9 * 64 + c];
        acc += x4 * sW[10 * 64 + c]; acc += x5 * sW[11 * 64 + c];
        XS[v * 64 + c] = acc;
    }
}

// generic fp32 GEMM: out[v][c] = act( sum_seg sum_k A_seg[v][k]*W[seg*64+k][c]
//                                     + bias[c]*(degscale?degscale[v]:1) )
__global__ void __launch_bounds__(256)
k_gemm64(const float* A0, const float* A1, const float* A2, const float* A3,
         int nA, const float* __restrict__ W, const float* __restrict__ bias,
         const float* __restrict__ degscale, float* __restrict__ out,
         int do_relu, int n)
{
    __shared__ float sW[64 * 64];
    __shared__ float sA[64 * 68];
    const int tid = threadIdx.x;
    const int rowBase = blockIdx.x * 64;
    const int c0 = (tid & 15) * 4;
    const int r0 = (tid >> 4) * 4;
    float acc[4][4] = {};
    const float* As[4] = {A0, A1, A2, A3};

    for (int seg = 0; seg < nA; ++seg) {
        const float* A = As[seg];
        const float4* Wv = (const float4*)(W + seg * 64 * 64);
        #pragma unroll
        for (int i = 0; i < 4; ++i)
            ((float4*)sW)[tid + i * 256] = Wv[tid + i * 256];
        int lr = tid >> 4;
        int lc = (tid & 15) * 4;
        #pragma unroll
        for (int i = 0; i < 4; ++i) {
            int r = lr + i * 16;
            int gr = rowBase + r;
            float4 v = make_float4(0.f, 0.f, 0.f, 0.f);
            if (gr < n) v = *(const float4*)(A + (size_t)gr * 64 + lc);
            *(float4*)(&sA[r * 68 + lc]) = v;
        }
        __syncthreads();
        #pragma unroll
        for (int k = 0; k < 64; ++k) {
            float4 b = *(const float4*)(&sW[k * 64 + c0]);
            float a0 = sA[(r0 + 0) * 68 + k];
            float a1 = sA[(r0 + 1) * 68 + k];
            float a2 = sA[(r0 + 2) * 68 + k];
            float a3 = sA[(r0 + 3) * 68 + k];
            acc[0][0] += a0 * b.x; acc[0][1] += a0 * b.y; acc[0][2] += a0 * b.z; acc[0][3] += a0 * b.w;
            acc[1][0] += a1 * b.x; acc[1][1] += a1 * b.y; acc[1][2] += a1 * b.z; acc[1][3] += a1 * b.w;
            acc[2][0] += a2 * b.x; acc[2][1] += a2 * b.y; acc[2][2] += a2 * b.z; acc[2][3] += a2 * b.w;
            acc[3][0] += a3 * b.x; acc[3][1] += a3 * b.y; acc[3][2] += a3 * b.z; acc[3][3] += a3 * b.w;
        }
        __syncthreads();
    }

    float4 bv = make_float4(0.f, 0.f, 0.f, 0.f);
    if (bias) bv = *(const float4*)(bias + c0);
    #pragma unroll
    for (int i = 0; i < 4; ++i) {
        int gr = rowBase + r0 + i;
        if (gr < n) {
            float s = degscale ? degscale[gr] : 1.0f;
            float4 o;
            o.x = acc[i][0] + bv.x * s;
            o.y = acc[i][1] + bv.y * s;
            o.z = acc[i][2] + bv.z * s;
            o.w = acc[i][3] + bv.w * s;
            if (do_relu) {
                o.x = fmaxf(o.x, 0.f); o.y = fmaxf(o.y, 0.f);
                o.z = fmaxf(o.z, 0.f); o.w = fmaxf(o.w, 0.f);
            }
            *(float4*)(out + (size_t)gr * 64 + c0) = o;
        }
    }
}

// dual GEMM: out0 = A@Wa + ba, out1 = A@Wb  (A tile loaded once)
__global__ void __launch_bounds__(256)
k_gemm64_dual(const float* __restrict__ A, const float* __restrict__ Wa,
              const float* __restrict__ ba, const float* __restrict__ Wb,
              float* __restrict__ out0, float* __restrict__ out1, int n)
{
    __shared__ float sW[64 * 64];
    __shared__ float sA[64 * 68];
    const int tid = threadIdx.x;
    const int rowBase = blockIdx.x * 64;
    const int c0 = (tid & 15) * 4;
    const int r0 = (tid >> 4) * 4;
    const int lr = tid >> 4;
    const int lc = (tid & 15) * 4;

    #pragma unroll
    for (int i = 0; i < 4; ++i) {
        int r = lr + i * 16;
        int gr = rowBase + r;
        float4 v = make_float4(0.f, 0.f, 0.f, 0.f);
        if (gr < n) v = *(const float4*)(A + (size_t)gr * 64 + lc);
        *(float4*)(&sA[r * 68 + lc]) = v;
    }

    #pragma unroll
    for (int half = 0; half < 2; ++half) {
        const float4* Wv = (const float4*)(half ? Wb : Wa);
        #pragma unroll
        for (int i = 0; i < 4; ++i)
            ((float4*)sW)[tid + i * 256] = Wv[tid + i * 256];
        __syncthreads();
        float acc[4][4] = {};
        #pragma unroll
        for (int k = 0; k < 64; ++k) {
            float4 b = *(const float4*)(&sW[k * 64 + c0]);
            float a0 = sA[(r0 + 0) * 68 + k];
            float a1 = sA[(r0 + 1) * 68 + k];
            float a2 = sA[(r0 + 2) * 68 + k];
            float a3 = sA[(r0 + 3) * 68 + k];
            acc[0][0] += a0 * b.x; acc[0][1] += a0 * b.y; acc[0][2] += a0 * b.z; acc[0][3] += a0 * b.w;
            acc[1][0] += a1 * b.x; acc[1][1] += a1 * b.y; acc[1][2] += a1 * b.z; acc[1][3] += a1 * b.w;
            acc[2][0] += a2 * b.x; acc[2][1] += a2 * b.y; acc[2][2] += a2 * b.z; acc[2][3] += a2 * b.w;
            acc[3][0] += a3 * b.x; acc[3][1] += a3 * b.y; acc[3][2] += a3 * b.z; acc[3][3] += a3 * b.w;
        }
        float4 bv = make_float4(0.f, 0.f, 0.f, 0.f);
        if (half == 0 && ba) bv = *(const float4*)(ba + c0);
        float* outp = half ? out1 : out0;
        #pragma unroll
        for (int i = 0; i < 4; ++i) {
            int gr = rowBase + r0 + i;
            if (gr < n) {
                float4 o;
                o.x = acc[i][0] + bv.x; o.y = acc[i][1] + bv.y;
                o.z = acc[i][2] + bv.z; o.w = acc[i][3] + bv.w;
                *(float4*)(outp + (size_t)gr * 64 + c0) = o;
            }
        }
        __syncthreads();
    }
}

// edge aggregation: agg[v] = sum_{e in in(v)} relu( XDb[v] + XS[src_e] + ea_e@W1e )
// half-warp per edge: lanes 0-15 handle edge e, lanes 16-31 edge e+1,
// float4 per lane -> one LDG covers two source rows.
__global__ void __launch_bounds__(256)
k_edge(const float* __restrict__ XDb, const float* __restrict__ XS,
       const float* __restrict__ W1e, float* __restrict__ agg)
{
    __shared__ float sE[5 * 64];
    int tid = threadIdx.x;
    for (int i = tid; i < 5 * 64; i += 256) sE[i] = W1e[i];
    __syncthreads();
    int wid = (blockIdx.x * 256 + tid) >> 5;
    int lane = tid & 31;
    if (wid >= NN) return;
    int half = lane >> 4;
    int hl = lane & 15;
    int c0 = hl * 4;
    float4 xd = *(const float4*)(XDb + (size_t)wid * 64 + c0);
    float4 w[5];
    #pragma unroll
    for (int k = 0; k < 5; ++k) w[k] = *(const float4*)(sE + k * 64 + c0);
    int e0 = g_ptr[wid], e1 = g_ptr[wid + 1];
    float4 acc = make_float4(0.f, 0.f, 0.f, 0.f);
    int e = e0;
    // 2 pairs (4 edges) per iteration for MLP
    for (; e + 3 < e1; e += 4) {
        int sa = g_src[e + half];
        int sb = g_src[e + 2 + half];
        float qa = (hl < 5) ? g_ea5[(size_t)(e + half) * 5 + hl] : 0.f;
        float qb = (hl < 5) ? g_ea5[(size_t)(e + 2 + half) * 5 + hl] : 0.f;
        float4 va = *(const float4*)(XS + (size_t)sa * 64 + c0);
        float4 vb = *(const float4*)(XS + (size_t)sb * 64 + c0);
        float pa0 = xd.x + va.x, pa1 = xd.y + va.y, pa2 = xd.z + va.z, pa3 = xd.w + va.w;
        float pb0 = xd.x + vb.x, pb1 = xd.y + vb.y, pb2 = xd.z + vb.z, pb3 = xd.w + vb.w;
        #pragma unroll
        for (int k = 0; k < 5; ++k) {
            float ea = __shfl_sync(0xffffffffu, qa, k, 16);
            float eb = __shfl_sync(0xffffffffu, qb, k, 16);
            pa0 += ea * w[k].x; pa1 += ea * w[k].y; pa2 += ea * w[k].z; pa3 += ea * w[k].w;
            pb0 += eb * w[k].x; pb1 += eb * w[k].y; pb2 += eb * w[k].z; pb3 += eb * w[k].w;
        }
        acc.x += fmaxf(pa0, 0.f) + fmaxf(pb0, 0.f);
        acc.y += fmaxf(pa1, 0.f) + fmaxf(pb1, 0.f);
        acc.z += fmaxf(pa2, 0.f) + fmaxf(pb2, 0.f);
        acc.w += fmaxf(pa3, 0.f) + fmaxf(pb3, 0.f);
    }
    // one pair
    for (; e + 1 < e1; e += 2) {
        int s = g_src[e + half];
        float q = (hl < 5) ? g_ea5[(size_t)(e + half) * 5 + hl] : 0.f;
        float4 v = *(const float4*)(XS + (size_t)s * 64 + c0);
        float p0 = xd.x + v.x, p1 = xd.y + v.y, p2 = xd.z + v.z, p3 = xd.w + v.w;
        #pragma unroll
        for (int k = 0; k < 5; ++k) {
            float ek = __shfl_sync(0xffffffffu, q, k, 16);
            p0 += ek * w[k].x; p1 += ek * w[k].y; p2 += ek * w[k].z; p3 += ek * w[k].w;
        }
        acc.x += fmaxf(p0, 0.f); acc.y += fmaxf(p1, 0.f);
        acc.z += fmaxf(p2, 0.f); acc.w += fmaxf(p3, 0.f);
    }
    // singleton tail: all lanes compute edge e (both halves load the same row,
    // shuffles stay converged); only lower half accumulates.
    if (e < e1) {
        int s = g_src[e];
        float q = (hl < 5) ? g_ea5[(size_t)e * 5 + hl] : 0.f;
        float4 v = *(const float4*)(XS + (size_t)s * 64 + c0);
        float p0 = xd.x + v.x, p1 = xd.y + v.y, p2 = xd.z + v.z, p3 = xd.w + v.w;
        #pragma unroll
        for (int k = 0; k < 5; ++k) {
            float ek = __shfl_sync(0xffffffffu, q, k, 16);
            p0 += ek * w[k].x; p1 += ek * w[k].y; p2 += ek * w[k].z; p3 += ek * w[k].w;
        }
        if (half == 0) {
            acc.x += fmaxf(p0, 0.f); acc.y += fmaxf(p1, 0.f);
            acc.z += fmaxf(p2, 0.f); acc.w += fmaxf(p3, 0.f);
        }
    }
    // combine halves
    acc.x += __shfl_xor_sync(0xffffffffu, acc.x, 16);
    acc.y += __shfl_xor_sync(0xffffffffu, acc.y, 16);
    acc.z += __shfl_xor_sync(0xffffffffu, acc.z, 16);
    acc.w += __shfl_xor_sync(0xffffffffu, acc.w, 16);
    if (half == 0)
        *(float4*)(agg + (size_t)wid * 64 + c0) = acc;
}

// TAGConv propagation: Hn[v] = dis[v] * sum_e dis[src_e] * H[src_e]
// half-warp per edge, float4 per lane.
__global__ void __launch_bounds__(256)
k_prop(const float* __restrict__ H, float* __restrict__ Hn)
{
    int tid = threadIdx.x;
    int wid = (blockIdx.x * 256 + tid) >> 5;
    int lane = tid & 31;
    if (wid >= NN) return;
    int half = lane >> 4;
    int hl = lane & 15;
    int c0 = hl * 4;
    float dd = g_dis[wid];
    int e0 = g_ptr[wid], e1 = g_ptr[wid + 1];
    float4 acc = make_float4(0.f, 0.f, 0.f, 0.f);
    int e = e0;
    // 4 pairs (8 edges) per iteration for MLP
    for (; e + 7 < e1; e += 8) {
        int s0 = g_src[e + half];
        int s1 = g_src[e + 2 + half];
        int s2 = g_src[e + 4 + half];
        int s3 = g_src[e + 6 + half];
        float n0 = g_dis[s0], n1 = g_dis[s1], n2 = g_dis[s2], n3 = g_dis[s3];
        float4 v0 = *(const float4*)(H + (size_t)s0 * 64 + c0);
        float4 v1 = *(const float4*)(H + (size_t)s1 * 64 + c0);
        float4 v2 = *(const float4*)(H + (size_t)s2 * 64 + c0);
        float4 v3 = *(const float4*)(H + (size_t)s3 * 64 + c0);
        acc.x += n0 * v0.x + n1 * v1.x + n2 * v2.x + n3 * v3.x;
        acc.y += n0 * v0.y + n1 * v1.y + n2 * v2.y + n3 * v3.y;
        acc.z += n0 * v0.z + n1 * v1.z + n2 * v2.z + n3 * v3.z;
        acc.w += n0 * v0.w + n1 * v1.w + n2 * v2.w + n3 * v3.w;
    }
    for (; e + 1 < e1; e += 2) {
        int s = g_src[e + half];
        float nr = g_dis[s];
        float4 v = *(const float4*)(H + (size_t)s * 64 + c0);
        acc.x += nr * v.x; acc.y += nr * v.y;
        acc.z += nr * v.z; acc.w += nr * v.w;
    }
    if (e < e1 && half == 0) {
        int s = g_src[e];
        float nr = g_dis[s];
        float4 v = *(const float4*)(H + (size_t)s * 64 + c0);
        acc.x += nr * v.x; acc.y += nr * v.y;
        acc.z += nr * v.z; acc.w += nr * v.w;
    }
    acc.x += __shfl_xor_sync(0xffffffffu, acc.x, 16);
    acc.y += __shfl_xor_sync(0xffffffffu, acc.y, 16);
    acc.z += __shfl_xor_sync(0xffffffffu, acc.z, 16);
    acc.w += __shfl_xor_sync(0xffffffffu, acc.w, 16);
    if (half == 0) {
        float4 o = make_float4(dd * acc.x, dd * acc.y, dd * acc.z, dd * acc.w);
        *(float4*)(Hn + (size_t)wid * 64 + c0) = o;
    }
}

// final layer post: out[v][c] = agg[v][:]@W2[:,c] + deg[v]*b2[c]   (64x6, no relu)
__global__ void __launch_bounds__(192)
k_post_last(const float* __restrict__ agg, const float* __restrict__ W2,
            const float* __restrict__ b2, float* __restrict__ out)
{
    __shared__ float sW[64 * 6];
    __shared__ float sb[6];
    int tid = threadIdx.x;
    for (int i = tid; i < 64 * 6; i += 192) sW[i] = W2[i];
    if (tid < 6) sb[tid] = b2[tid];
    __syncthreads();
    int gid = blockIdx.x * 192 + tid;
    int v = gid / 6;
    int c = gid - v * 6;
    if (v >= NN) return;
    const float* ar = agg + (size_t)v * 64;
    float acc = 0.f;
    #pragma unroll
    for (int k = 0; k < 64; ++k) acc += ar[k] * sW[k * 6 + c];
    out[v * 6 + c] = acc + g_deg[v] * sb[c];
}

// ---------------- host ----------------

extern "C" void kernel_launch(void* const* d_in, const int* in_sizes, int n_in,
                              void* d_out, int out_size)
{
    const float* data_x     = (const float*)d_in[0];
    const int*   edge_index = (const int*)  d_in[1];
    const float* edge_attr  = (const float*)d_in[2];
    const float* ea0_W1     = (const float*)d_in[3];
    const float* ea0_b1     = (const float*)d_in[4];
    const float* ea0_W2     = (const float*)d_in[5];
    const float* ea0_b2     = (const float*)d_in[6];
    const float* eam_W1     = (const float*)d_in[7];
    const float* eam_b1     = (const float*)d_in[8];
    const float* eam_W2     = (const float*)d_in[9];
    const float* eam_b2     = (const float*)d_in[10];
    const float* eal_W1     = (const float*)d_in[11];
    const float* eal_b1     = (const float*)d_in[12];
    const float* eal_W2     = (const float*)d_in[13];
    const float* eal_b2     = (const float*)d_in[14];
    const float* tag_W      = (const float*)d_in[15];
    const float* tag_b      = (const float*)d_in[16];
    float* out = (float*)d_out;

    float* pBuf = nullptr;
    float* pDeg = nullptr;
    cudaGetSymbolAddress((void**)&pBuf, g_buf);
    cudaGetSymbolAddress((void**)&pDeg, g_deg);
    float* B0 = pBuf + 0 * (size_t)NN * HH;
    float* B1 = pBuf + 1 * (size_t)NN * HH;
    float* B2 = pBuf + 2 * (size_t)NN * HH;
    float* B3 = pBuf + 3 * (size_t)NN * HH;
    float* B4 = pBuf + 4 * (size_t)NN * HH;

    const int EB = (EE + 255) / 256;
    const int WB = (NN * 32 + 255) / 256;
    const int GB = (NN + 63) / 64;

    // CSR build
    k_zero_counts<<<(NN + 255) / 256, 256>>>();
    k_count<<<EB, 256>>>(edge_index);
    k_scan<<<1, 1024>>>();
    k_scatter<<<EB, 256>>>(edge_index, edge_attr);

    // layer 1: edge_agg ea0  (x = data_x[:,4:10])
    k_pre0<<<(NN * 128 + 255) / 256, 256>>>(data_x, ea0_W1, ea0_b1, B0, B1);
    k_edge<<<WB, 256>>>(B0, B1, ea0_W1 + 12 * 64, B2);
    k_gemm64<<<GB, 256>>>(B2, nullptr, nullptr, nullptr, 1, ea0_W2, ea0_b2, pDeg, B3, 1, NN);
    float* x = B3;

    for (int l = 0; l < 3; ++l) {
        // tagconv l
        k_prop<<<WB, 256>>>(x, B0);
        k_prop<<<WB, 256>>>(B0, B1);
        k_prop<<<WB, 256>>>(B1, B2);
        k_gemm64<<<GB, 256>>>(x, B0, B1, B2, 4, tag_W + (size_t)l * 4 * 64 * 64,
                              tag_b + l * 64, nullptr, B4, 1, NN);
        x = B4;

        if (l < 2) {
            // mid edge_agg l
            const float* W1 = eam_W1 + (size_t)l * 133 * 64;
            const float* b1 = eam_b1 + l * 64;
            const float* W2 = eam_W2 + (size_t)l * 64 * 64;
            const float* b2 = eam_b2 + l * 64;
            k_gemm64_dual<<<GB, 256>>>(x, W1, b1, W1 + 64 * 64, B0, B1, NN);
            k_edge<<<WB, 256>>>(B0, B1, W1 + 128 * 64, B2);
            k_gemm64<<<GB, 256>>>(B2, nullptr, nullptr, nullptr, 1, W2, b2, pDeg, B3, 1, NN);
            x = B3;
        }
    }

    // final edge_agg (64 -> 6)
    k_gemm64_dual<<<GB, 256>>>(x, eal_W1, eal_b1, eal_W1 + 64 * 64, B0, B1, NN);
    k_edge<<<WB, 256>>>(B0, B1, eal_W1 + 128 * 64, B2);
    k_post_last<<<(NN * 6 + 191) / 192, 192>>>(B2, eal_W2, eal_b2, out);
}